// round 16
// baseline (speedup 1.0000x reference)
#include <cuda_runtime.h>
#include <cuda_fp16.h>

#define T_LEN 2048
#define E_N   19
#define B_N   64

typedef unsigned int u32;

// final hidden states: [b][e][dir*32+u]
__device__ float g_hfinal[B_N * E_N * 64];

__device__ __forceinline__ float tanh_ap(float x) {
    float r;
    asm("tanh.approx.f32 %0, %1;" : "=f"(r) : "f"(x));
    return r;
}
__device__ __forceinline__ u32 pack_hf2(float lo, float hi) {
    __half2 p;
    p.x = __float2half(lo);
    p.y = __float2half(hi);
    return *(u32*)&p;
}

// D += A(16x16 fp16, row-major) * B(16x8 fp16, col-major), fp32 accumulate
__device__ __forceinline__ void mma16816(float d[4], const u32 a[4], u32 b0, u32 b1) {
    asm volatile(
        "mma.sync.aligned.m16n8k16.row.col.f32.f16.f16.f32 "
        "{%0,%1,%2,%3}, {%4,%5,%6,%7}, {%8,%9}, {%0,%1,%2,%3};"
        : "+f"(d[0]), "+f"(d[1]), "+f"(d[2]), "+f"(d[3])
        : "r"(a[0]), "r"(a[1]), "r"(a[2]), "r"(a[3]), "r"(b0), "r"(b1));
}

// One CTA = one (e,dir) x 4 batch items, 4 warps. 608 CTAs = 4 per SM on
// GB300's 152 SMs -> four INDEPENDENT barrier domains per SM, so the CTAs
// drift out of phase and MUFU/tensor/LSU phases overlap across CTAs
// (vs 2 phase-locked domains in the 304-CTA kernel).
// Warp w owns units 8w..8w+7; M-rows permuted [i(8);f(8);g(8);o(8)].
// Items occupy MMA columns 0..3 (cols 4..7 stay zero). After the MMA an
// 8-shfl redistribution gives each thread all 4 gates of (unit u, item tig)
// -> 5 fp32 tanh per thread (4 gates + cell), fp32 seeds and cell path
// (the proven 9.8e-5 numerics).
// h layout pos(u) = ((u&7)>>1)*8 + 2w + (u&1) -> single LDS.128;
// double-buffered bsm; x pipelined via shfl.
__global__ void __launch_bounds__(128, 4)
lstm_kernel(const float* __restrict__ x,      // [B, T, E]
            const float* __restrict__ w_ih,   // [E, 2, 128]
            const float* __restrict__ w_hh,   // [E, 2, 128, 32]
            const float* __restrict__ b_ih,   // [E, 2, 128]
            const float* __restrict__ b_hh)   // [E, 2, 128]
{
    __shared__ __half bsm[2][8][32];   // [buf][item][pos(u)]; rows 4..7 stay 0

    const int tid  = threadIdx.x;
    const int w    = tid >> 5;
    const int lane = tid & 31;
    const int grp  = lane >> 2;
    const int tig  = lane & 3;

    const int ed = blockIdx.x >> 4;          // 0..37
    const int b0 = (blockIdx.x & 15) * 4;    // 4-item group
    const int e  = ed >> 1;
    const int d  = ed & 1;

    const int u     = 8 * w + grp;
    const int pos_u = (grp >> 1) * 8 + 2 * w + (grp & 1);

    // ---- A fragments: m-tile mt rows = [gate 2mt units; gate 2mt+1 units] ----
    u32 A[2][2][4];
    {
        const float* Wp = w_hh + ed * 128 * 32;
#pragma unroll
        for (int mt = 0; mt < 2; mt++) {
            const int g0 = 2 * mt, g1 = 2 * mt + 1;
            const float C0 = (g0 == 2) ? 1.0f : 0.5f;
            const float C1 = (g1 == 2) ? 1.0f : 0.5f;
            const float* r0 = Wp + (g0 * 32 + u) * 32;
            const float* r1 = Wp + (g1 * 32 + u) * 32;
#pragma unroll
            for (int kt = 0; kt < 2; kt++) {
                const int kb = 16 * kt + 2 * tig;
                A[mt][kt][0] = pack_hf2(r0[kb] * C0,     r0[kb + 1] * C0);
                A[mt][kt][1] = pack_hf2(r1[kb] * C1,     r1[kb + 1] * C1);
                A[mt][kt][2] = pack_hf2(r0[kb + 8] * C0, r0[kb + 9] * C0);
                A[mt][kt][3] = pack_hf2(r1[kb + 8] * C1, r1[kb + 9] * C1);
            }
        }
    }

    // input weight / bias for unit u, gates 0..3 (activation scale folded)
    float wihC[4], biasC[4];
#pragma unroll
    for (int g = 0; g < 4; g++) {
        const float Cg = (g == 2) ? 1.0f : 0.5f;
        const int row = ed * 128 + g * 32 + u;
        wihC[g]  = Cg * w_ih[row];
        biasC[g] = Cg * (b_ih[row] + b_hh[row]);
    }

    // ---- zero both h buffers (h0 = 0): 2*8*32 halves = 256 u32 ----
    for (int i = tid; i < 256; i += 128) ((u32*)bsm)[i] = 0u;

    // ---- x pipeline: lane owns item lane&3 ----
    const int tstart = d ? (T_LEN - 1) : 0;
    const int stride = d ? -E_N : E_N;
    const float* xp = x + ((long long)(b0 + (lane & 3)) * T_LEN + tstart) * E_N + e;
    float xq  = __ldg(xp);
    xp += stride;
    float xqn = __ldg(xp);

    const int it0 = 2 * tig, it1 = 2 * tig + 1;   // MMA cols (dups for tig>=2)

    // seeds for t=0 (MMA column layout; cols >= 4 are dups, unused)
    float Dn[2][4];
    {
        const float xv0 = __shfl_sync(0xffffffffu, xq, it0 & 3);
        const float xv1 = __shfl_sync(0xffffffffu, xq, it1 & 3);
#pragma unroll
        for (int mt = 0; mt < 2; mt++) {
            Dn[mt][0] = fmaf(xv0, wihC[2 * mt],     biasC[2 * mt]);
            Dn[mt][1] = fmaf(xv1, wihC[2 * mt],     biasC[2 * mt]);
            Dn[mt][2] = fmaf(xv0, wihC[2 * mt + 1], biasC[2 * mt + 1]);
            Dn[mt][3] = fmaf(xv1, wihC[2 * mt + 1], biasC[2 * mt + 1]);
        }
    }

    float c0 = 0.f, h0 = 0.f;

    __syncthreads();

#pragma unroll 1
    for (int t = 0; t < T_LEN; t++) {
        // ---- single LDS.128: thread's 4 B-frag words are contiguous ----
        const uint4 v = *(const uint4*)&bsm[t & 1][grp][8 * tig];

        // ---- split accumulators: Da = seed + ktile0, Db = 0 + ktile1 ----
        float Da[2][4], Db[2][4];
#pragma unroll
        for (int mt = 0; mt < 2; mt++)
#pragma unroll
            for (int j = 0; j < 4; j++) { Da[mt][j] = Dn[mt][j]; Db[mt][j] = 0.f; }

        mma16816(Da[0], A[0][0], v.x, v.y);
        mma16816(Db[0], A[0][1], v.z, v.w);
        mma16816(Da[1], A[1][0], v.x, v.y);
        mma16816(Db[1], A[1][1], v.z, v.w);

        // ---- redistribute gates so thread owns (u, item = tig) ----
        float Dm[2][4];
#pragma unroll
        for (int mt = 0; mt < 2; mt++)
#pragma unroll
            for (int j = 0; j < 4; j++) Dm[mt][j] = Da[mt][j] + Db[mt][j];

        const int src = grp * 4 + (tig >> 1);
        const float gia = __shfl_sync(0xffffffffu, Dm[0][0], src);
        const float gib = __shfl_sync(0xffffffffu, Dm[0][1], src);
        const float gfa = __shfl_sync(0xffffffffu, Dm[0][2], src);
        const float gfb = __shfl_sync(0xffffffffu, Dm[0][3], src);
        const float gga = __shfl_sync(0xffffffffu, Dm[1][0], src);
        const float ggb = __shfl_sync(0xffffffffu, Dm[1][1], src);
        const float goa = __shfl_sync(0xffffffffu, Dm[1][2], src);
        const float gob = __shfl_sync(0xffffffffu, Dm[1][3], src);
        const bool odd = (tig & 1);
        const float gi = odd ? gib : gia;
        const float gf = odd ? gfb : gfa;
        const float gg = odd ? ggb : gga;
        const float go = odd ? gob : goa;

        // ---- activations + c/h update (5 fp32 tanh / thread) ----
        const float si = fmaf(0.5f, tanh_ap(gi), 0.5f);
        const float sf = fmaf(0.5f, tanh_ap(gf), 0.5f);
        const float sg = tanh_ap(gg);
        const float so = fmaf(0.5f, tanh_ap(go), 0.5f);
        c0 = fmaf(sf, c0, si * sg);
        h0 = so * tanh_ap(c0);
        bsm[(t + 1) & 1][tig][pos_u] = __float2half(h0);   // rows 4-7 stay 0

        // ---- epilogue (off-chain): seeds for t+1 ----
        {
            const float xv0n = __shfl_sync(0xffffffffu, xqn, it0 & 3);
            const float xv1n = __shfl_sync(0xffffffffu, xqn, it1 & 3);
#pragma unroll
            for (int mt = 0; mt < 2; mt++) {
                Dn[mt][0] = fmaf(xv0n, wihC[2 * mt],     biasC[2 * mt]);
                Dn[mt][1] = fmaf(xv1n, wihC[2 * mt],     biasC[2 * mt]);
                Dn[mt][2] = fmaf(xv0n, wihC[2 * mt + 1], biasC[2 * mt + 1]);
                Dn[mt][3] = fmaf(xv1n, wihC[2 * mt + 1], biasC[2 * mt + 1]);
            }
            if (t + 2 < T_LEN) xp += stride;
            xqn = __ldg(xp);
        }
        __syncthreads();
    }

    g_hfinal[((b0 + tig) * E_N + e) * 64 + d * 32 + u] = h0;
}

// Per-batch epilogue: per-electrode LayerNorm over 64 features, electrode mean, FC.
__global__ void __launch_bounds__(64)
head_kernel(const float* __restrict__ ln_gamma,
            const float* __restrict__ ln_beta,
            const float* __restrict__ fc_w,
            const float* __restrict__ fc_b,
            float* __restrict__ out)
{
    const int b = blockIdx.x;
    const int f = threadIdx.x;
    __shared__ float red[4];
    const float* hbp = g_hfinal + b * (E_N * 64);

    float pooled = 0.f;
    for (int e = 0; e < E_N; e++) {
        float v = hbp[e * 64 + f];
        float s = v, s2 = v * v;
#pragma unroll
        for (int off = 16; off; off >>= 1) {
            s  += __shfl_xor_sync(0xffffffffu, s,  off);
            s2 += __shfl_xor_sync(0xffffffffu, s2, off);
        }
        if ((f & 31) == 0) { red[(f >> 5) * 2] = s; red[(f >> 5) * 2 + 1] = s2; }
        __syncthreads();
        float S = red[0] + red[2], S2 = red[1] + red[3];
        __syncthreads();
        float mu  = S * (1.0f / 64.0f);
        float var = fmaf(-mu, mu, S2 * (1.0f / 64.0f));
        float nv  = (v - mu) * rsqrtf(var + 1e-5f);
        pooled += fmaf(nv, ln_gamma[e * 64 + f], ln_beta[e * 64 + f]);
    }
    pooled *= (1.0f / (float)E_N);

    float a = pooled * fc_w[f];
#pragma unroll
    for (int off = 16; off; off >>= 1) a += __shfl_xor_sync(0xffffffffu, a, off);
    if ((f & 31) == 0) red[f >> 5] = a;
    __syncthreads();
    if (f == 0) out[b] = red[0] + red[1] + fc_b[0];
}

extern "C" void kernel_launch(void* const* d_in, const int* in_sizes, int n_in,
                              void* d_out, int out_size) {
    const float* x        = (const float*)d_in[0];
    const float* w_ih     = (const float*)d_in[1];
    const float* w_hh     = (const float*)d_in[2];
    const float* b_ih     = (const float*)d_in[3];
    const float* b_hh     = (const float*)d_in[4];
    const float* ln_gamma = (const float*)d_in[5];
    const float* ln_beta  = (const float*)d_in[6];
    const float* fc_w     = (const float*)d_in[7];
    const float* fc_b     = (const float*)d_in[8];
    float* out = (float*)d_out;

    lstm_kernel<<<E_N * 2 * 16, 128>>>(x, w_ih, w_hh, b_ih, b_hh);
    head_kernel<<<B_N, 64>>>(ln_gamma, ln_beta, fc_w, fc_b, out);
}

// round 17
// speedup vs baseline: 1.2225x; 1.2225x over previous
#include <cuda_runtime.h>
#include <cuda_fp16.h>

#define T_LEN 2048
#define E_N   19
#define B_N   64

typedef unsigned int u32;

// final hidden states: [b][e][dir*32+u]
__device__ float g_hfinal[B_N * E_N * 64];

__device__ __forceinline__ float tanh_ap(float x) {
    float r;
    asm("tanh.approx.f32 %0, %1;" : "=f"(r) : "f"(x));
    return r;
}

__device__ __forceinline__ u32 pack_hf2(float lo, float hi) {
    __half2 p;
    p.x = __float2half(lo);    // low 16 bits = lower k index
    p.y = __float2half(hi);
    return *(u32*)&p;
}

// D += A(16x16 fp16, row-major) * B(16x8 fp16, col-major), fp32 accumulate
__device__ __forceinline__ void mma16816(float d[4], const u32 a[4], u32 b0, u32 b1) {
    asm volatile(
        "mma.sync.aligned.m16n8k16.row.col.f32.f16.f16.f32 "
        "{%0,%1,%2,%3}, {%4,%5,%6,%7}, {%8,%9}, {%0,%1,%2,%3};"
        : "+f"(d[0]), "+f"(d[1]), "+f"(d[2]), "+f"(d[3])
        : "r"(a[0]), "r"(a[1]), "r"(a[2]), "r"(a[3]), "r"(b0), "r"(b1));
}

// One CTA = one (e,dir) x 8 batch items, 4 warps; 304 CTAs = exactly
// 2 CTAs/SM on GB300's 152 SMs (uniform).
// Warp w owns units 8w..8w+7; M-rows permuted [i(8);f(8);g(8);o(8)] so each
// thread holds all four gates for (unit u, items it0/it1) after the MMA.
// vs the 398us champion: accumulators are seed-initialized and the two
// K-tiles are CHAINED into the same accumulator (R8-proven numerics),
// deleting 8 zero-inits + 8 merge-FADDs per warp-step (~23% of issue slots).
// h layout pos(u) = ((u&7)>>1)*8 + 2w + (u&1) -> single LDS.128;
// double-buffered bsm; x pipelined via shfl; seeds computed in the epilogue.
__global__ void __launch_bounds__(128)
lstm_kernel(const float* __restrict__ x,      // [B, T, E]
            const float* __restrict__ w_ih,   // [E, 2, 128]
            const float* __restrict__ w_hh,   // [E, 2, 128, 32]
            const float* __restrict__ b_ih,   // [E, 2, 128]
            const float* __restrict__ b_hh)   // [E, 2, 128]
{
    __shared__ __half bsm[2][8][32];   // [buf][item][pos(u)] fp16 h, 64B rows

    const int tid  = threadIdx.x;
    const int w    = tid >> 5;
    const int lane = tid & 31;
    const int grp  = lane >> 2;
    const int tig  = lane & 3;

    const int ed = blockIdx.x >> 3;
    const int b0 = (blockIdx.x & 7) * 8;
    const int e  = ed >> 1;
    const int d  = ed & 1;

    const int u     = 8 * w + grp;
    const int pos_u = (grp >> 1) * 8 + 2 * w + (grp & 1);

    // ---- A fragments: m-tile mt rows = [gate 2mt units; gate 2mt+1 units] ----
    u32 A[2][2][4];
    {
        const float* Wp = w_hh + ed * 128 * 32;
#pragma unroll
        for (int mt = 0; mt < 2; mt++) {
            const int g0 = 2 * mt, g1 = 2 * mt + 1;
            const float C0 = (g0 == 2) ? 1.0f : 0.5f;
            const float C1 = (g1 == 2) ? 1.0f : 0.5f;
            const float* r0 = Wp + (g0 * 32 + u) * 32;
            const float* r1 = Wp + (g1 * 32 + u) * 32;
#pragma unroll
            for (int kt = 0; kt < 2; kt++) {
                const int kb = 16 * kt + 2 * tig;
                A[mt][kt][0] = pack_hf2(r0[kb] * C0,     r0[kb + 1] * C0);
                A[mt][kt][1] = pack_hf2(r1[kb] * C1,     r1[kb + 1] * C1);
                A[mt][kt][2] = pack_hf2(r0[kb + 8] * C0, r0[kb + 9] * C0);
                A[mt][kt][3] = pack_hf2(r1[kb + 8] * C1, r1[kb + 9] * C1);
            }
        }
    }

    // input weight / bias for unit u, gates 0..3 (activation scale folded)
    float wihC[4], biasC[4];
#pragma unroll
    for (int g = 0; g < 4; g++) {
        const float Cg = (g == 2) ? 1.0f : 0.5f;
        const int row = ed * 128 + g * 32 + u;
        wihC[g]  = Cg * w_ih[row];
        biasC[g] = Cg * (b_ih[row] + b_hh[row]);
    }

    // ---- zero both h buffers (h0 = 0): 2*8*32 halves = 256 u32 ----
    for (int i = tid; i < 256; i += 128) ((u32*)bsm)[i] = 0u;

    // ---- x pipeline: lane owns item lane&7 ----
    const int tstart = d ? (T_LEN - 1) : 0;
    const int stride = d ? -E_N : E_N;
    const float* xp = x + ((long long)(b0 + (lane & 7)) * T_LEN + tstart) * E_N + e;
    float xq  = __ldg(xp);
    xp += stride;
    float xqn = __ldg(xp);

    const int it0 = 2 * tig, it1 = 2 * tig + 1;

    // seeds for t=0
    float Dn[2][4];
    {
        const float xv0 = __shfl_sync(0xffffffffu, xq, it0);
        const float xv1 = __shfl_sync(0xffffffffu, xq, it1);
#pragma unroll
        for (int mt = 0; mt < 2; mt++) {
            Dn[mt][0] = fmaf(xv0, wihC[2 * mt],     biasC[2 * mt]);
            Dn[mt][1] = fmaf(xv1, wihC[2 * mt],     biasC[2 * mt]);
            Dn[mt][2] = fmaf(xv0, wihC[2 * mt + 1], biasC[2 * mt + 1]);
            Dn[mt][3] = fmaf(xv1, wihC[2 * mt + 1], biasC[2 * mt + 1]);
        }
    }

    float c0 = 0.f, c1 = 0.f, h0 = 0.f, h1 = 0.f;

    __syncthreads();

#pragma unroll 1
    for (int t = 0; t < T_LEN; t++) {
        // ---- single LDS.128: thread's 4 B-frag words are contiguous ----
        const uint4 v = *(const uint4*)&bsm[t & 1][grp][8 * tig];

        // ---- seed-initialized accumulators, chained depth-2 HMMA ----
        float D[2][4];
#pragma unroll
        for (int mt = 0; mt < 2; mt++)
#pragma unroll
            for (int j = 0; j < 4; j++) D[mt][j] = Dn[mt][j];

        mma16816(D[0], A[0][0], v.x, v.y);
        mma16816(D[0], A[0][1], v.z, v.w);
        mma16816(D[1], A[1][0], v.x, v.y);
        mma16816(D[1], A[1][1], v.z, v.w);

        // ---- activations + c/h update (fp32 tanh) ----
        const float si0 = fmaf(0.5f, tanh_ap(D[0][0]), 0.5f);
        const float si1 = fmaf(0.5f, tanh_ap(D[0][1]), 0.5f);
        const float sf0 = fmaf(0.5f, tanh_ap(D[0][2]), 0.5f);
        const float sf1 = fmaf(0.5f, tanh_ap(D[0][3]), 0.5f);
        const float sg0 = tanh_ap(D[1][0]);
        const float sg1 = tanh_ap(D[1][1]);
        const float so0 = fmaf(0.5f, tanh_ap(D[1][2]), 0.5f);
        const float so1 = fmaf(0.5f, tanh_ap(D[1][3]), 0.5f);
        c0 = fmaf(sf0, c0, si0 * sg0);
        c1 = fmaf(sf1, c1, si1 * sg1);
        h0 = so0 * tanh_ap(c0);
        h1 = so1 * tanh_ap(c1);

        // ---- write h to the NEXT buffer ----
        bsm[(t + 1) & 1][it0][pos_u] = __float2half(h0);
        bsm[(t + 1) & 1][it1][pos_u] = __float2half(h1);

        // ---- epilogue (off-chain): seeds for t+1 from prefetched x ----
        {
            const float xv0n = __shfl_sync(0xffffffffu, xqn, it0);
            const float xv1n = __shfl_sync(0xffffffffu, xqn, it1);
#pragma unroll
            for (int mt = 0; mt < 2; mt++) {
                Dn[mt][0] = fmaf(xv0n, wihC[2 * mt],     biasC[2 * mt]);
                Dn[mt][1] = fmaf(xv1n, wihC[2 * mt],     biasC[2 * mt]);
                Dn[mt][2] = fmaf(xv0n, wihC[2 * mt + 1], biasC[2 * mt + 1]);
                Dn[mt][3] = fmaf(xv1n, wihC[2 * mt + 1], biasC[2 * mt + 1]);
            }
            if (t + 2 < T_LEN) xp += stride;
            xqn = __ldg(xp);
        }
        __syncthreads();
    }

    g_hfinal[((b0 + it0) * E_N + e) * 64 + d * 32 + u] = h0;
    g_hfinal[((b0 + it1) * E_N + e) * 64 + d * 32 + u] = h1;
}

// Per-batch epilogue: per-electrode LayerNorm over 64 features, electrode mean, FC.
__global__ void __launch_bounds__(64)
head_kernel(const float* __restrict__ ln_gamma,
            const float* __restrict__ ln_beta,
            const float* __restrict__ fc_w,
            const float* __restrict__ fc_b,
            float* __restrict__ out)
{
    const int b = blockIdx.x;
    const int f = threadIdx.x;
    __shared__ float red[4];
    const float* hbp = g_hfinal + b * (E_N * 64);

    float pooled = 0.f;
    for (int e = 0; e < E_N; e++) {
        float v = hbp[e * 64 + f];
        float s = v, s2 = v * v;
#pragma unroll
        for (int off = 16; off; off >>= 1) {
            s  += __shfl_xor_sync(0xffffffffu, s,  off);
            s2 += __shfl_xor_sync(0xffffffffu, s2, off);
        }
        if ((f & 31) == 0) { red[(f >> 5) * 2] = s; red[(f >> 5) * 2 + 1] = s2; }
        __syncthreads();
        float S = red[0] + red[2], S2 = red[1] + red[3];
        __syncthreads();
        float mu  = S * (1.0f / 64.0f);
        float var = fmaf(-mu, mu, S2 * (1.0f / 64.0f));
        float nv  = (v - mu) * rsqrtf(var + 1e-5f);
        pooled += fmaf(nv, ln_gamma[e * 64 + f], ln_beta[e * 64 + f]);
    }
    pooled *= (1.0f / (float)E_N);

    float a = pooled * fc_w[f];
#pragma unroll
    for (int off = 16; off; off >>= 1) a += __shfl_xor_sync(0xffffffffu, a, off);
    if ((f & 31) == 0) red[f >> 5] = a;
    __syncthreads();
    if (f == 0) out[b] = red[0] + red[1] + fc_b[0];
}

extern "C" void kernel_launch(void* const* d_in, const int* in_sizes, int n_in,
                              void* d_out, int out_size) {
    const float* x        = (const float*)d_in[0];
    const float* w_ih     = (const float*)d_in[1];
    const float* w_hh     = (const float*)d_in[2];
    const float* b_ih     = (const float*)d_in[3];
    const float* b_hh     = (const float*)d_in[4];
    const float* ln_gamma = (const float*)d_in[5];
    const float* ln_beta  = (const float*)d_in[6];
    const float* fc_w     = (const float*)d_in[7];
    const float* fc_b     = (const float*)d_in[8];
    float* out = (float*)d_out;

    lstm_kernel<<<E_N * 2 * 8, 128>>>(x, w_ih, w_hh, b_ih, b_hh);
    head_kernel<<<B_N, 64>>>(ln_gamma, ln_beta, fc_w, fc_b, out);
}